// round 15
// baseline (speedup 1.0000x reference)
#include <cuda_runtime.h>
#include <cuda_fp16.h>
#include <math.h>

#define T_LEN   2048
#define TMASK   2047
#define NKEEP   1536
#define EDGE    256
#define NBC     16
#define NBAND   80
#define PHA_NB  50
#define AMP_NB  30
#define NBINS   18
#define NKTOT   640
#define NEV     160
#define KCH     80
#define NCH     8
#define KB_DFT  (NKTOT / 4)     // 160 k per dft block
#define ZS      8               // K z-split in mi
#define KZB     (NKEEP / ZS)    // 192 t per mi z-chunk
#define PW      5               // p's (warps) per mi block

// ---------------- f32x2 packed helpers (sm_103a) -----------------------------
typedef unsigned long long u64;
__device__ __forceinline__ u64 pk2(float lo, float hi) {
    u64 d; asm("mov.b64 %0,{%1,%2};" : "=l"(d) : "f"(lo), "f"(hi)); return d;
}
__device__ __forceinline__ void up2(u64 v, float& lo, float& hi) {
    asm("mov.b64 {%0,%1},%2;" : "=f"(lo), "=f"(hi) : "l"(v));
}
__device__ __forceinline__ u64 fma2(u64 a, u64 b, u64 c) {
    u64 d; asm("fma.rn.f32x2 %0,%1,%2,%3;" : "=l"(d) : "l"(a), "l"(b), "l"(c)); return d;
}
__device__ __forceinline__ u64 add2(u64 a, u64 b) {
    u64 d; asm("add.rn.f32x2 %0,%1,%2;" : "=l"(d) : "l"(a), "l"(b)); return d;
}
__device__ __forceinline__ u64 mul2(u64 a, u64 b) {
    u64 d; asm("mul.rn.f32x2 %0,%1,%2;" : "=l"(d) : "l"(a), "l"(b)); return d;
}

// ---------------- compile-time tables ---------------------------------------
struct Tables {
    int evk[NEV];
    int evslot[NEV];
    int evstart[NCH + 1];
    int cha[NBAND];
    int chb[NBAND];
};

constexpr Tables make_tables() {
    Tables tb{};
    int klo[NBAND] = {}, khi[NBAND] = {};
    for (int b = 0; b < NBAND; b++) {
        double lo_d = 0.0, hi_d = 0.0;
        if (b < PHA_NB) {
            double step = 18.0 / 49.0;
            double mid  = (b == PHA_NB - 1) ? 20.0 : ((double)b * step + 2.0);
            lo_d = mid * 0.75; hi_d = mid * 1.25;
        } else {
            int i = b - PHA_NB;
            double step = (141.0 - 60.0) / 29.0;
            double mid  = (i == AMP_NB - 1) ? 141.0 : ((double)i * step + 60.0);
            lo_d = mid * 0.875; hi_d = mid * 1.125;
        }
        float lo = (float)lo_d, hi = (float)hi_d;
        int kl = -1, kh = -2;
        for (int k = 1; k < NKTOT; k++) {
            float f = (float)k * 0.25f;
            if (f >= lo && f <= hi) { if (kl < 0) kl = k; kh = k; }
        }
        klo[b] = kl; khi[b] = kh;
        tb.cha[b] = (kl - 1) / KCH;
        tb.chb[b] = kh / KCH;
    }
    int key[NEV] = {}, slot[NEV] = {};
    for (int e = 0; e < NEV; e++) {
        int b = e >> 1, type = e & 1;
        key[e]  = type ? khi[b] : (klo[b] - 1);
        slot[e] = e;
    }
    for (int i = 1; i < NEV; i++) {
        int k2 = key[i], s2 = slot[i], j = i - 1;
        while (j >= 0 && key[j] > k2) { key[j+1] = key[j]; slot[j+1] = slot[j]; j--; }
        key[j+1] = k2; slot[j+1] = s2;
    }
    for (int e = 0; e < NEV; e++) { tb.evk[e] = key[e]; tb.evslot[e] = slot[e]; }
    for (int c = 0; c <= NCH; c++) {
        int s = 0;
        while (s < NEV && key[s] < c * KCH) s++;
        tb.evstart[c] = s;
    }
    return tb;
}
__constant__ Tables c_tab = make_tables();

// ---------------- scratch -----------------------------------------------------
__device__ float2        g_Xf[NBC][NKTOT];
__device__ float2        g_pref[NBC][NEV][NKEEP];
__device__ float2        g_ctot[NCH - 1][NBC][NKEEP];
__device__ unsigned char g_pidx[NBC][PHA_NB][NKEEP];
__device__ __half        g_ampH[NBC][32][NKEEP];     // channel-major; ch30=1, ch31=0
__device__ float         g_part[NBC][PHA_NB][ZS][24][32];
__device__ int           g_cnt[NBC][PHA_NB];

// ---------------- kernel 1: fused 2-stage DFT, B split in quarters ----------
__global__ __launch_bounds__(1024) void dft_kernel(const float* __restrict__ x) {
    __shared__ float  s_x[T_LEN];
    __shared__ float  s_twr[T_LEN], s_twi[T_LEN];
    __shared__ float  s_Yr[32 * 65], s_Yi[32 * 65];
    __shared__ float2 s_tw64[64];
    int bc = blockIdx.x, by = blockIdx.y, tid = threadIdx.x;
    if (by == 0 && tid < PHA_NB) g_cnt[bc][tid] = 0;   // reset mi counters
    for (int j = tid; j < T_LEN; j += 1024) {
        float s, c;
        sincospif((float)j * (1.0f / 1024.0f), &s, &c);
        s_twr[j] = c; s_twi[j] = s;
        s_x[j] = x[bc * T_LEN + j];
    }
    if (tid < 64) {
        float s, c;
        sincospif((float)tid * (1.0f / 32.0f), &s, &c);
        s_tw64[tid] = make_float2(c, -s);
    }
    __syncthreads();

    int b  = tid & 31;
    int mg = tid >> 5;
#pragma unroll
    for (int half = 0; half < 2; half++) {
        int m = mg + 32 * half;
        float ar = 0.f, ai = 0.f;
#pragma unroll 8
        for (int a = 0; a < 64; a++) {
            float  xv = s_x[(a << 5) + b];
            float2 w  = s_tw64[(m * a) & 63];
            ar = fmaf(xv, w.x, ar);
            ai = fmaf(xv, w.y, ai);
        }
        s_Yr[b * 65 + m] = ar;
        s_Yi[b * 65 + m] = ai;
    }
    __syncthreads();

    if (tid < KB_DFT) {
        int k  = by * KB_DFT + tid;
        int km = k & 63;
        float ar = 0.f, ai = 0.f;
#pragma unroll 8
        for (int b2 = 0; b2 < 32; b2++) {
            float yr = s_Yr[b2 * 65 + km];
            float yi = s_Yi[b2 * 65 + km];
            int id = (k * b2) & TMASK;
            float wr = s_twr[id], wi = s_twi[id];
            ar += yr * wr + yi * wi;
            ai += yi * wr - yr * wi;
        }
        g_Xf[bc][k] = make_float2(ar, ai);
    }
}

// ---------------- kernel 2: chunked prefix sweep, f32x2 packed --------------
__global__ __launch_bounds__(128) void prefix_kernel() {
    __shared__ float2 s_XF[KCH];
    __shared__ float2 s_XG[KCH];
    int bc  = blockIdx.y;
    int ch  = blockIdx.z;
    int k0  = ch * KCH;
    int tid = threadIdx.x;
    for (int j = tid; j < KCH; j += 128) {
        float2 X = g_Xf[bc][k0 + j];
        s_XF[j] = X;
        s_XG[j] = make_float2(-X.y, X.x);
    }
    __syncthreads();

    int tk = blockIdx.x * 128 + tid;
    int t  = EDGE + tk;
    float wr_, wi_;
    sincospif((float)t * (1.0f / 1024.0f), &wi_, &wr_);
    u64 Wr  = pk2(wr_, wr_);
    u64 Wi  = pk2(wi_, wi_);
    u64 WiN = pk2(-wi_, -wi_);
    float zr_, zi_;
    {
        int m = (k0 * t) & TMASK;
        sincospif((float)m * (1.0f / 1024.0f), &zi_, &zr_);
    }
    u64 Zr = pk2(zr_, zr_);
    u64 Zi = pk2(zi_, zi_);
    u64 Sa = 0ull, Sb = 0ull;

    int j    = c_tab.evstart[ch];
    int jend = c_tab.evstart[ch + 1];
    int nev  = (j < jend) ? c_tab.evk[j] : (1 << 30);

#pragma unroll
    for (int g = 0; g < KCH / 16; g++) {
        u64 Ca = 0ull, Cb = 0ull;
#pragma unroll
        for (int kk = 0; kk < 16; kk++) {
            int ks = g * 16 + kk;
            int k  = k0 + ks;
            u64 XF = *(const u64*)&s_XF[ks];
            u64 XG = *(const u64*)&s_XG[ks];
            Ca = fma2(Zr, XF, Ca);
            Cb = fma2(Zi, XG, Cb);
            if (k == nev) {
                do {
                    u64 tot = add2(add2(Sa, Ca), add2(Sb, Cb));
                    float vr, vi; up2(tot, vr, vi);
                    g_pref[bc][c_tab.evslot[j]][tk] = make_float2(vr, vi);
                    j++;
                    nev = (j < jend) ? c_tab.evk[j] : (1 << 30);
                } while (k == nev);
            }
            u64 nZr = fma2(Zi, WiN, mul2(Zr, Wr));
            u64 nZi = fma2(Zi, Wr,  mul2(Zr, Wi));
            Zr = nZr; Zi = nZi;
        }
        Sa = add2(Sa, Ca);
        Sb = add2(Sb, Cb);
    }
    if (ch < NCH - 1) {
        u64 tot = add2(Sa, Sb);
        float vr, vi; up2(tot, vr, vi);
        g_ctot[ch][bc][tk] = make_float2(vr, vi);
    }
}

// ---------------- kernel 3: band tail -- snapshots + chunk-prefix -----------
__global__ __launch_bounds__(128) void tail_kernel() {
    __shared__ float s_cumr[NCH][129], s_cumi[NCH][129];
    int bc  = blockIdx.y;
    int bg  = blockIdx.z;
    int tid = threadIdx.x;
    int tk  = blockIdx.x * 128 + tid;

    float cr = 0.f, ci = 0.f;
    s_cumr[0][tid] = 0.f; s_cumi[0][tid] = 0.f;
#pragma unroll
    for (int ch = 1; ch < NCH; ch++) {
        float2 T = g_ctot[ch - 1][bc][tk];
        cr += T.x; ci += T.y;
        s_cumr[ch][tid] = cr; s_cumi[ch][tid] = ci;
    }
    __syncthreads();

    const float PIF    = 3.14159274101257324f;
    const float WIDTHF = (float)(2.0 * M_PI / (double)NBINS);
#pragma unroll
    for (int bb = 0; bb < 16; bb++) {
        int b = bg * 16 + bb;
        float2 pa = g_pref[bc][2 * b][tk];
        float2 pb = g_pref[bc][2 * b + 1][tk];
        int ca = c_tab.cha[b], cb = c_tab.chb[b];
        float re = (pb.x + s_cumr[cb][tid]) - (pa.x + s_cumr[ca][tid]);
        float im = (pb.y + s_cumi[cb][tid]) - (pa.y + s_cumi[ca][tid]);
        if (b < PHA_NB) {
            float ang = atan2f(im, re);
            float q   = __fdiv_rn(ang + PIF, WIDTHF);
            int   idx = (int)floorf(q);
            idx = max(0, min(idx, NBINS - 1));
            g_pidx[bc][b][tk] = (unsigned char)idx;
        } else {
            int a = b - PHA_NB;
            g_ampH[bc][a][tk] = __float2half_rn(sqrtf(re * re + im * im));
        }
    }
    if (bg == 4) {                      // count row + zero pad row
        g_ampH[bc][30][tk] = __float2half_rn(1.0f);
        g_ampH[bc][31][tk] = __float2half_rn(0.0f);
    }
}

// ---------------- kernel 4: binned sums via HMMA, warp-autonomous ------------
// grid (10, 16, 8), block 160 (5 warps). Warp w owns p = bx*5 + w, z-chunk z.
// All warps share the same A fragments (L1 reuse x5); zero intra-block
// reduction; per-warp counter epilogue computes MI on the last z.
__global__ __launch_bounds__(160, 5) void mi_mma_kernel(float* __restrict__ out) {
    __shared__ unsigned char s_bin[PW][KZB];          // 960 B
    __shared__ float s_sum[PW][32][25];               // 16 KB
    int bc   = blockIdx.y;
    int z    = blockIdx.z;
    int tid  = threadIdx.x;
    int w    = tid >> 5;
    int lane = tid & 31;
    int gid  = lane >> 2;       // 0..7
    int tig  = lane & 3;        // 0..3
    int p    = blockIdx.x * PW + w;

    // each warp loads its own p's bin bytes (192 B = 12 uint4)
    {
        const uint4* src = (const uint4*)&g_pidx[bc][p][z * KZB];
        uint4* dst = (uint4*)&s_bin[w][0];
        if (lane < KZB / 16) dst[lane] = src[lane];
    }
    __syncwarp();

    const __half* ampb = &g_ampH[bc][0][0];
    float d[6][4];
#pragma unroll
    for (int i = 0; i < 6; i++)
#pragma unroll
        for (int r = 0; r < 4; r++) d[i][r] = 0.f;

    unsigned int nsplat[3];
#pragma unroll
    for (int nt = 0; nt < 3; nt++)
        nsplat[nt] = (unsigned int)(nt * 8 + gid) * 0x01010101u;

#pragma unroll
    for (int ks = 0; ks < KZB / 16; ks++) {           // 12 ksteps
        int k0 = z * KZB + ks * 16;
        // ---- A fragments (amp): identical across the 5 warps -> L1 hits ----
        unsigned int a[2][4];
#pragma unroll
        for (int mt = 0; mt < 2; mt++) {
            const __half* r0 = ampb + (mt * 16 + gid) * NKEEP + k0 + 2 * tig;
            const __half* r1 = r0 + 8 * NKEEP;
            a[mt][0] = *(const unsigned int*)r0;
            a[mt][1] = *(const unsigned int*)r1;
            a[mt][2] = *(const unsigned int*)(r0 + 8);
            a[mt][3] = *(const unsigned int*)(r1 + 8);
        }
        int tl = ks * 16 + 2 * tig;
        unsigned int blo = *(const unsigned short*)&s_bin[w][tl];
        unsigned int bhi = *(const unsigned short*)&s_bin[w][tl + 8];
        unsigned int wpk = blo | (bhi << 16);
#pragma unroll
        for (int nt = 0; nt < 3; nt++) {
            unsigned int c2  = __vcmpeq4(wpk, nsplat[nt]);
            unsigned int bb0 = __byte_perm(c2, 0, 0x1100) & 0x3C003C00u;
            unsigned int bb1 = __byte_perm(c2, 0, 0x3322) & 0x3C003C00u;
#pragma unroll
            for (int mt = 0; mt < 2; mt++) {
                float* dd = d[mt * 3 + nt];
                asm volatile(
                    "mma.sync.aligned.m16n8k16.row.col.f32.f16.f16.f32 "
                    "{%0,%1,%2,%3},{%4,%5,%6,%7},{%8,%9},{%0,%1,%2,%3};"
                    : "+f"(dd[0]), "+f"(dd[1]), "+f"(dd[2]), "+f"(dd[3])
                    : "r"(a[mt][0]), "r"(a[mt][1]), "r"(a[mt][2]), "r"(a[mt][3]),
                      "r"(bb0), "r"(bb1));
            }
        }
    }

    // ---- warp-owned z-partial: direct store, no block reduce ----
#pragma unroll
    for (int i = 0; i < 6; i++)
#pragma unroll
        for (int r = 0; r < 4; r++)
            g_part[bc][p][z][i * 4 + r][lane] = d[i][r];

    // ---- per-warp counter; winner reduces over z + MI ----
    __threadfence();
    int old = 0;
    if (lane == 0) old = atomicAdd(&g_cnt[bc][p], 1);
    old = __shfl_sync(0xffffffffu, old, 0);
    if (old != ZS - 1) return;
    __threadfence();

    float dd[6][4];
#pragma unroll
    for (int i = 0; i < 6; i++)
#pragma unroll
        for (int r = 0; r < 4; r++) {
            float v = 0.f;
#pragma unroll
            for (int zz = 0; zz < ZS; zz++)
                v += g_part[bc][p][zz][i * 4 + r][lane];
            dd[i][r] = v;
        }
    // scatter D -> s_sum[w][ch][bin]
#pragma unroll
    for (int mt = 0; mt < 2; mt++)
#pragma unroll
        for (int nt = 0; nt < 3; nt++) {
            float* dr = dd[mt * 3 + nt];
            int ch0 = mt * 16 + gid;
            int cb  = nt * 8 + 2 * tig;
            s_sum[w][ch0][cb]         = dr[0];
            s_sum[w][ch0][cb + 1]     = dr[1];
            s_sum[w][ch0 + 8][cb]     = dr[2];
            s_sum[w][ch0 + 8][cb + 1] = dr[3];
        }
    __syncwarp();

    float means[NBINS];
    float tot = 0.f;
#pragma unroll
    for (int k = 0; k < NBINS; k++) {
        float cnt = s_sum[w][30][k];
        float s   = s_sum[w][lane][k];
        float m   = __fdiv_rn(s, fmaxf(cnt, 1e-9f));
        means[k]  = m;
        tot      += m;
    }
    float denom = fmaxf(tot, 1e-9f);
    float acc = 0.f;
#pragma unroll
    for (int k = 0; k < NBINS; k++) {
        float pr = __fdiv_rn(means[k], denom);
        acc += pr * logf(pr + 1e-9f);
    }
    const float LOG_NB = 2.8903717578961645f;
    if (lane < AMP_NB)
        out[(bc * PHA_NB + p) * AMP_NB + lane] = (LOG_NB + acc) / LOG_NB;
}

// ---------------- launch -----------------------------------------------------
extern "C" void kernel_launch(void* const* d_in, const int* in_sizes, int n_in,
                              void* d_out, int out_size) {
    const float* x = (const float*)d_in[0];
    float* out = (float*)d_out;

    dft_kernel<<<dim3(NBC, 4), 1024>>>(x);
    prefix_kernel<<<dim3(NKEEP / 128, NBC, NCH), 128>>>();
    tail_kernel<<<dim3(NKEEP / 128, NBC, 5), 128>>>();
    mi_mma_kernel<<<dim3(PHA_NB / PW, NBC, ZS), 160>>>(out);
}

// round 16
// speedup vs baseline: 1.2213x; 1.2213x over previous
#include <cuda_runtime.h>
#include <cuda_fp16.h>
#include <math.h>

#define T_LEN   2048
#define TMASK   2047
#define NKEEP   1536
#define EDGE    256
#define NBC     16
#define NBAND   80
#define PHA_NB  50
#define AMP_NB  30
#define NBINS   18
#define NKTOT   640
#define NEV     160
#define KCH     80
#define NCH     8
#define KB_DFT  (NKTOT / 4)     // 160 k per dft block
#define ZS      8               // K z-split in mi
#define KZB     (NKEEP / ZS)    // 192 t per mi z-chunk
#define PW      5               // p's (warps) per mi block
#define APAD2   200             // staged amp row pitch (halves): banks 4*gid+tig

// ---------------- f32x2 packed helpers (sm_103a) -----------------------------
typedef unsigned long long u64;
__device__ __forceinline__ u64 pk2(float lo, float hi) {
    u64 d; asm("mov.b64 %0,{%1,%2};" : "=l"(d) : "f"(lo), "f"(hi)); return d;
}
__device__ __forceinline__ void up2(u64 v, float& lo, float& hi) {
    asm("mov.b64 {%0,%1},%2;" : "=f"(lo), "=f"(hi) : "l"(v));
}
__device__ __forceinline__ u64 fma2(u64 a, u64 b, u64 c) {
    u64 d; asm("fma.rn.f32x2 %0,%1,%2,%3;" : "=l"(d) : "l"(a), "l"(b), "l"(c)); return d;
}
__device__ __forceinline__ u64 add2(u64 a, u64 b) {
    u64 d; asm("add.rn.f32x2 %0,%1,%2;" : "=l"(d) : "l"(a), "l"(b)); return d;
}
__device__ __forceinline__ u64 mul2(u64 a, u64 b) {
    u64 d; asm("mul.rn.f32x2 %0,%1,%2;" : "=l"(d) : "l"(a), "l"(b)); return d;
}

// ---------------- compile-time tables ---------------------------------------
struct Tables {
    int evk[NEV];
    int evslot[NEV];
    int evstart[NCH + 1];
    int cha[NBAND];
    int chb[NBAND];
};

constexpr Tables make_tables() {
    Tables tb{};
    int klo[NBAND] = {}, khi[NBAND] = {};
    for (int b = 0; b < NBAND; b++) {
        double lo_d = 0.0, hi_d = 0.0;
        if (b < PHA_NB) {
            double step = 18.0 / 49.0;
            double mid  = (b == PHA_NB - 1) ? 20.0 : ((double)b * step + 2.0);
            lo_d = mid * 0.75; hi_d = mid * 1.25;
        } else {
            int i = b - PHA_NB;
            double step = (141.0 - 60.0) / 29.0;
            double mid  = (i == AMP_NB - 1) ? 141.0 : ((double)i * step + 60.0);
            lo_d = mid * 0.875; hi_d = mid * 1.125;
        }
        float lo = (float)lo_d, hi = (float)hi_d;
        int kl = -1, kh = -2;
        for (int k = 1; k < NKTOT; k++) {
            float f = (float)k * 0.25f;
            if (f >= lo && f <= hi) { if (kl < 0) kl = k; kh = k; }
        }
        klo[b] = kl; khi[b] = kh;
        tb.cha[b] = (kl - 1) / KCH;
        tb.chb[b] = kh / KCH;
    }
    int key[NEV] = {}, slot[NEV] = {};
    for (int e = 0; e < NEV; e++) {
        int b = e >> 1, type = e & 1;
        key[e]  = type ? khi[b] : (klo[b] - 1);
        slot[e] = e;
    }
    for (int i = 1; i < NEV; i++) {
        int k2 = key[i], s2 = slot[i], j = i - 1;
        while (j >= 0 && key[j] > k2) { key[j+1] = key[j]; slot[j+1] = slot[j]; j--; }
        key[j+1] = k2; slot[j+1] = s2;
    }
    for (int e = 0; e < NEV; e++) { tb.evk[e] = key[e]; tb.evslot[e] = slot[e]; }
    for (int c = 0; c <= NCH; c++) {
        int s = 0;
        while (s < NEV && key[s] < c * KCH) s++;
        tb.evstart[c] = s;
    }
    return tb;
}
__constant__ Tables c_tab = make_tables();

// ---------------- scratch -----------------------------------------------------
__device__ float2        g_Xf[NBC][NKTOT];
__device__ float2        g_pref[NBC][NEV][NKEEP];
__device__ float2        g_ctot[NCH - 1][NBC][NKEEP];
__device__ unsigned char g_pidx[NBC][PHA_NB][NKEEP];
__device__ __half        g_ampH[NBC][32][NKEEP];     // channel-major; ch30=1, ch31=0
__device__ float         g_part[NBC][PHA_NB][ZS][24][32];
__device__ int           g_cnt[NBC][PHA_NB];

// ---------------- kernel 1: fused 2-stage DFT, B split in quarters ----------
__global__ __launch_bounds__(1024) void dft_kernel(const float* __restrict__ x) {
    __shared__ float  s_x[T_LEN];
    __shared__ float  s_twr[T_LEN], s_twi[T_LEN];
    __shared__ float  s_Yr[32 * 65], s_Yi[32 * 65];
    __shared__ float2 s_tw64[64];
    int bc = blockIdx.x, by = blockIdx.y, tid = threadIdx.x;
    if (by == 0 && tid < PHA_NB) g_cnt[bc][tid] = 0;   // reset mi counters
    for (int j = tid; j < T_LEN; j += 1024) {
        float s, c;
        sincospif((float)j * (1.0f / 1024.0f), &s, &c);
        s_twr[j] = c; s_twi[j] = s;
        s_x[j] = x[bc * T_LEN + j];
    }
    if (tid < 64) {
        float s, c;
        sincospif((float)tid * (1.0f / 32.0f), &s, &c);
        s_tw64[tid] = make_float2(c, -s);
    }
    __syncthreads();

    int b  = tid & 31;
    int mg = tid >> 5;
#pragma unroll
    for (int half = 0; half < 2; half++) {
        int m = mg + 32 * half;
        float ar = 0.f, ai = 0.f;
#pragma unroll 8
        for (int a = 0; a < 64; a++) {
            float  xv = s_x[(a << 5) + b];
            float2 w  = s_tw64[(m * a) & 63];
            ar = fmaf(xv, w.x, ar);
            ai = fmaf(xv, w.y, ai);
        }
        s_Yr[b * 65 + m] = ar;
        s_Yi[b * 65 + m] = ai;
    }
    __syncthreads();

    if (tid < KB_DFT) {
        int k  = by * KB_DFT + tid;
        int km = k & 63;
        float ar = 0.f, ai = 0.f;
#pragma unroll 8
        for (int b2 = 0; b2 < 32; b2++) {
            float yr = s_Yr[b2 * 65 + km];
            float yi = s_Yi[b2 * 65 + km];
            int id = (k * b2) & TMASK;
            float wr = s_twr[id], wi = s_twi[id];
            ar += yr * wr + yi * wi;
            ai += yi * wr - yr * wi;
        }
        g_Xf[bc][k] = make_float2(ar, ai);
    }
}

// ---------------- kernel 2: chunked prefix sweep, f32x2 packed --------------
__global__ __launch_bounds__(128) void prefix_kernel() {
    __shared__ float2 s_XF[KCH];
    __shared__ float2 s_XG[KCH];
    int bc  = blockIdx.y;
    int ch  = blockIdx.z;
    int k0  = ch * KCH;
    int tid = threadIdx.x;
    for (int j = tid; j < KCH; j += 128) {
        float2 X = g_Xf[bc][k0 + j];
        s_XF[j] = X;
        s_XG[j] = make_float2(-X.y, X.x);
    }
    __syncthreads();

    int tk = blockIdx.x * 128 + tid;
    int t  = EDGE + tk;
    float wr_, wi_;
    sincospif((float)t * (1.0f / 1024.0f), &wi_, &wr_);
    u64 Wr  = pk2(wr_, wr_);
    u64 Wi  = pk2(wi_, wi_);
    u64 WiN = pk2(-wi_, -wi_);
    float zr_, zi_;
    {
        int m = (k0 * t) & TMASK;
        sincospif((float)m * (1.0f / 1024.0f), &zi_, &zr_);
    }
    u64 Zr = pk2(zr_, zr_);
    u64 Zi = pk2(zi_, zi_);
    u64 Sa = 0ull, Sb = 0ull;

    int j    = c_tab.evstart[ch];
    int jend = c_tab.evstart[ch + 1];
    int nev  = (j < jend) ? c_tab.evk[j] : (1 << 30);

#pragma unroll
    for (int g = 0; g < KCH / 16; g++) {
        u64 Ca = 0ull, Cb = 0ull;
#pragma unroll
        for (int kk = 0; kk < 16; kk++) {
            int ks = g * 16 + kk;
            int k  = k0 + ks;
            u64 XF = *(const u64*)&s_XF[ks];
            u64 XG = *(const u64*)&s_XG[ks];
            Ca = fma2(Zr, XF, Ca);
            Cb = fma2(Zi, XG, Cb);
            if (k == nev) {
                do {
                    u64 tot = add2(add2(Sa, Ca), add2(Sb, Cb));
                    float vr, vi; up2(tot, vr, vi);
                    g_pref[bc][c_tab.evslot[j]][tk] = make_float2(vr, vi);
                    j++;
                    nev = (j < jend) ? c_tab.evk[j] : (1 << 30);
                } while (k == nev);
            }
            u64 nZr = fma2(Zi, WiN, mul2(Zr, Wr));
            u64 nZi = fma2(Zi, Wr,  mul2(Zr, Wi));
            Zr = nZr; Zi = nZi;
        }
        Sa = add2(Sa, Ca);
        Sb = add2(Sb, Cb);
    }
    if (ch < NCH - 1) {
        u64 tot = add2(Sa, Sb);
        float vr, vi; up2(tot, vr, vi);
        g_ctot[ch][bc][tk] = make_float2(vr, vi);
    }
}

// ---------------- kernel 3: band tail -- snapshots + chunk-prefix -----------
__global__ __launch_bounds__(128) void tail_kernel() {
    __shared__ float s_cumr[NCH][129], s_cumi[NCH][129];
    int bc  = blockIdx.y;
    int bg  = blockIdx.z;
    int tid = threadIdx.x;
    int tk  = blockIdx.x * 128 + tid;

    float cr = 0.f, ci = 0.f;
    s_cumr[0][tid] = 0.f; s_cumi[0][tid] = 0.f;
#pragma unroll
    for (int ch = 1; ch < NCH; ch++) {
        float2 T = g_ctot[ch - 1][bc][tk];
        cr += T.x; ci += T.y;
        s_cumr[ch][tid] = cr; s_cumi[ch][tid] = ci;
    }
    __syncthreads();

    const float PIF    = 3.14159274101257324f;
    const float WIDTHF = (float)(2.0 * M_PI / (double)NBINS);
#pragma unroll
    for (int bb = 0; bb < 16; bb++) {
        int b = bg * 16 + bb;
        float2 pa = g_pref[bc][2 * b][tk];
        float2 pb = g_pref[bc][2 * b + 1][tk];
        int ca = c_tab.cha[b], cb = c_tab.chb[b];
        float re = (pb.x + s_cumr[cb][tid]) - (pa.x + s_cumr[ca][tid]);
        float im = (pb.y + s_cumi[cb][tid]) - (pa.y + s_cumi[ca][tid]);
        if (b < PHA_NB) {
            float ang = atan2f(im, re);
            float q   = __fdiv_rn(ang + PIF, WIDTHF);
            int   idx = (int)floorf(q);
            idx = max(0, min(idx, NBINS - 1));
            g_pidx[bc][b][tk] = (unsigned char)idx;
        } else {
            int a = b - PHA_NB;
            g_ampH[bc][a][tk] = __float2half_rn(sqrtf(re * re + im * im));
        }
    }
    if (bg == 4) {                      // count row + zero pad row
        g_ampH[bc][30][tk] = __float2half_rn(1.0f);
        g_ampH[bc][31][tk] = __float2half_rn(0.0f);
    }
}

// ---------------- kernel 4: HMMA, warp-autonomous + smem-staged A ------------
// grid (10, 16, 8), block 160 (5 warps). Warp w owns p = bx*5 + w, z-chunk z.
// A slice [32][192] staged in smem once per block (coalesced), fragments read
// as conflict-free LDS (pitch 200 halves -> bank 4*gid+tig). Zero intra-block
// reduction; per-warp counter epilogue emits MI on the last z.
__global__ __launch_bounds__(160) void mi_mma_kernel(float* __restrict__ out) {
    __shared__ __half s_amp[32][APAD2];               // 12.8 KB
    __shared__ unsigned char s_bin[PW][KZB];          // 960 B
    __shared__ float s_sum[PW][32][25];               // 16 KB
    int bc   = blockIdx.y;
    int z    = blockIdx.z;
    int tid  = threadIdx.x;
    int w    = tid >> 5;
    int lane = tid & 31;
    int gid  = lane >> 2;       // 0..7
    int tig  = lane & 3;        // 0..3
    int p    = blockIdx.x * PW + w;

    // stage amp slice [32][192] (coalesced uint4; 24 uint4 per row)
    for (int idx = tid; idx < 32 * (KZB / 8); idx += 160) {
        int row  = idx / (KZB / 8);
        int col8 = idx % (KZB / 8);
        *(uint4*)&s_amp[row][col8 * 8] =
            *(const uint4*)&g_ampH[bc][row][z * KZB + col8 * 8];
    }
    // each warp loads its own p's bin bytes (192 B = 12 uint4)
    {
        const uint4* src = (const uint4*)&g_pidx[bc][p][z * KZB];
        uint4* dst = (uint4*)&s_bin[w][0];
        if (lane < KZB / 16) dst[lane] = src[lane];
    }
    __syncthreads();

    float d[6][4];
#pragma unroll
    for (int i = 0; i < 6; i++)
#pragma unroll
        for (int r = 0; r < 4; r++) d[i][r] = 0.f;

    unsigned int nsplat[3];
#pragma unroll
    for (int nt = 0; nt < 3; nt++)
        nsplat[nt] = (unsigned int)(nt * 8 + gid) * 0x01010101u;

#pragma unroll
    for (int ks = 0; ks < KZB / 16; ks++) {           // 12 ksteps
        // ---- A fragments from smem: conflict-free LDS ----
        unsigned int a[2][4];
#pragma unroll
        for (int mt = 0; mt < 2; mt++) {
            const __half* r0 = &s_amp[mt * 16 + gid][ks * 16 + 2 * tig];
            const __half* r1 = &s_amp[mt * 16 + gid + 8][ks * 16 + 2 * tig];
            a[mt][0] = *(const unsigned int*)r0;
            a[mt][1] = *(const unsigned int*)r1;
            a[mt][2] = *(const unsigned int*)(r0 + 8);
            a[mt][3] = *(const unsigned int*)(r1 + 8);
        }
        int tl = ks * 16 + 2 * tig;
        unsigned int blo = *(const unsigned short*)&s_bin[w][tl];
        unsigned int bhi = *(const unsigned short*)&s_bin[w][tl + 8];
        unsigned int wpk = blo | (bhi << 16);
#pragma unroll
        for (int nt = 0; nt < 3; nt++) {
            unsigned int c2  = __vcmpeq4(wpk, nsplat[nt]);
            unsigned int bb0 = __byte_perm(c2, 0, 0x1100) & 0x3C003C00u;
            unsigned int bb1 = __byte_perm(c2, 0, 0x3322) & 0x3C003C00u;
#pragma unroll
            for (int mt = 0; mt < 2; mt++) {
                float* dd = d[mt * 3 + nt];
                asm volatile(
                    "mma.sync.aligned.m16n8k16.row.col.f32.f16.f16.f32 "
                    "{%0,%1,%2,%3},{%4,%5,%6,%7},{%8,%9},{%0,%1,%2,%3};"
                    : "+f"(dd[0]), "+f"(dd[1]), "+f"(dd[2]), "+f"(dd[3])
                    : "r"(a[mt][0]), "r"(a[mt][1]), "r"(a[mt][2]), "r"(a[mt][3]),
                      "r"(bb0), "r"(bb1));
            }
        }
    }

    // ---- warp-owned z-partial: direct store, no block reduce ----
#pragma unroll
    for (int i = 0; i < 6; i++)
#pragma unroll
        for (int r = 0; r < 4; r++)
            g_part[bc][p][z][i * 4 + r][lane] = d[i][r];

    // ---- per-warp counter; winner reduces over z + MI ----
    __threadfence();
    int old = 0;
    if (lane == 0) old = atomicAdd(&g_cnt[bc][p], 1);
    old = __shfl_sync(0xffffffffu, old, 0);
    if (old != ZS - 1) return;
    __threadfence();

    float dd[6][4];
#pragma unroll
    for (int i = 0; i < 6; i++)
#pragma unroll
        for (int r = 0; r < 4; r++) {
            float v = 0.f;
#pragma unroll
            for (int zz = 0; zz < ZS; zz++)
                v += g_part[bc][p][zz][i * 4 + r][lane];
            dd[i][r] = v;
        }
    // scatter D -> s_sum[w][ch][bin]
#pragma unroll
    for (int mt = 0; mt < 2; mt++)
#pragma unroll
        for (int nt = 0; nt < 3; nt++) {
            float* dr = dd[mt * 3 + nt];
            int ch0 = mt * 16 + gid;
            int cb  = nt * 8 + 2 * tig;
            s_sum[w][ch0][cb]         = dr[0];
            s_sum[w][ch0][cb + 1]     = dr[1];
            s_sum[w][ch0 + 8][cb]     = dr[2];
            s_sum[w][ch0 + 8][cb + 1] = dr[3];
        }
    __syncwarp();

    float means[NBINS];
    float tot = 0.f;
#pragma unroll
    for (int k = 0; k < NBINS; k++) {
        float cnt = s_sum[w][30][k];
        float s   = s_sum[w][lane][k];
        float m   = __fdiv_rn(s, fmaxf(cnt, 1e-9f));
        means[k]  = m;
        tot      += m;
    }
    float denom = fmaxf(tot, 1e-9f);
    float acc = 0.f;
#pragma unroll
    for (int k = 0; k < NBINS; k++) {
        float pr = __fdiv_rn(means[k], denom);
        acc += pr * logf(pr + 1e-9f);
    }
    const float LOG_NB = 2.8903717578961645f;
    if (lane < AMP_NB)
        out[(bc * PHA_NB + p) * AMP_NB + lane] = (LOG_NB + acc) / LOG_NB;
}

// ---------------- launch -----------------------------------------------------
extern "C" void kernel_launch(void* const* d_in, const int* in_sizes, int n_in,
                              void* d_out, int out_size) {
    const float* x = (const float*)d_in[0];
    float* out = (float*)d_out;

    dft_kernel<<<dim3(NBC, 4), 1024>>>(x);
    prefix_kernel<<<dim3(NKEEP / 128, NBC, NCH), 128>>>();
    tail_kernel<<<dim3(NKEEP / 128, NBC, 5), 128>>>();
    mi_mma_kernel<<<dim3(PHA_NB / PW, NBC, ZS), 160>>>(out);
}